// round 15
// baseline (speedup 1.0000x reference)
#include <cuda_runtime.h>
#include <cuda_fp16.h>
#include <cstdint>

#define NN 100000
#define EE 3200000
#define ET (EE + NN)           // 3,300,000 edges incl. self loops
#define HEADS 4
#define HD 64
#define D1 256                 // HEADS*HD
#define INDIM 128

// ---------------- scratch (static device globals; no allocs) ----------------
__device__ __half g_xh[(size_t)NN * INDIM]; // x (fp16)                   (25.6 MB)
__device__ __half g_h1h[(size_t)NN * D1];   // layer1 h (fp16)            (51.2 MB)
__device__ __half g_g1h[(size_t)NN * D1];   // elu(agg1+b1) (fp16)        (51.2 MB)
__device__ __half g_h2h[(size_t)NN * HD];   // layer2 h (fp16)            (12.8 MB)
__device__ float g_as1[NN * HEADS];
__device__ float g_ad1[NN * HEADS];
__device__ float g_as2[NN];
__device__ float g_ad2[NN];
__device__ int   g_deg[NN];                 // zero at entry of every launch
__device__ int   g_rowptr[NN + 1];
__device__ int   g_cursor[NN];
__device__ int   g_blksums[256];
__device__ int   g_srcs[ET];                // CSR-by-dst src indices (13.2 MB)

__device__ __forceinline__ float lrelu(float x) { return fmaxf(x, 0.2f * x); }
__device__ __forceinline__ float eluf(float x)  { return x > 0.f ? x : expm1f(x); }

#define SM_OFF 8.0f   // constant softmax offset (exact in ratio; avoids overflow)

__device__ __forceinline__ void mma_f16(float* d, const unsigned* a, const unsigned* b) {
    asm volatile(
        "mma.sync.aligned.m16n8k16.row.col.f32.f16.f16.f32 "
        "{%0,%1,%2,%3}, {%4,%5,%6,%7}, {%8,%9}, {%0,%1,%2,%3};\n"
        : "+f"(d[0]), "+f"(d[1]), "+f"(d[2]), "+f"(d[3])
        : "r"(a[0]), "r"(a[1]), "r"(a[2]), "r"(a[3]), "r"(b[0]), "r"(b[1]));
}

__device__ __forceinline__ void ldsm_x4(unsigned* r, unsigned addr) {
    asm volatile("ldmatrix.sync.aligned.m8n8.x4.shared.b16 {%0,%1,%2,%3}, [%4];"
                 : "=r"(r[0]), "=r"(r[1]), "=r"(r[2]), "=r"(r[3]) : "r"(addr));
}
__device__ __forceinline__ void ldsm_x4_t(unsigned* r, unsigned addr) {
    asm volatile("ldmatrix.sync.aligned.m8n8.x4.trans.shared.b16 {%0,%1,%2,%3}, [%4];"
                 : "=r"(r[0]), "=r"(r[1]), "=r"(r[2]), "=r"(r[3]) : "r"(addr));
}
__device__ __forceinline__ void cp_async16(unsigned dst, const void* src) {
    asm volatile("cp.async.cg.shared.global [%0], [%1], 16;" :: "r"(dst), "l"(src));
}

// ---------------- x -> fp16 pre-convert ----------------
__global__ void k_xh(const float* __restrict__ x) {
    int i = blockIdx.x * blockDim.x + threadIdx.x;   // 8 elems per thread
    if (i >= NN * INDIM / 8) return;
    const float4* p = (const float4*)x + (size_t)i * 2;
    float4 f0 = p[0], f1 = p[1];
    __half2 h[4];
    h[0] = __floats2half2_rn(f0.x, f0.y);
    h[1] = __floats2half2_rn(f0.z, f0.w);
    h[2] = __floats2half2_rn(f1.x, f1.y);
    h[3] = __floats2half2_rn(f1.z, f1.w);
    *(uint4*)(g_xh + (size_t)i * 8) = *(uint4*)h;
}

// ---------------- fp16 tensor-core GEMM, fully-staged, zero-sync mainloop ----
template<int N, int K, int BN, int NH, int SSTR>
__device__ __forceinline__ void mma_gemm(const __half* __restrict__ Ah,
                                         const float* __restrict__ Bg,
                                         __half* __restrict__ C, int M,
                                         const float* __restrict__ av,
                                         const float* __restrict__ dv,
                                         float* __restrict__ sOut,
                                         float* __restrict__ dOut) {
    constexpr int BM = 128, BK = 16;
    constexpr int WN = BN / 2;
    constexpr int NTI = WN / 8;
    constexpr int KPA = K + 8;
    constexpr int NPAD = BN + 8;
    constexpr int NT = K / BK;

    extern __shared__ __align__(16) __half dynsm[];
    __half* As = dynsm;                          // BM * KPA
    __half* Bs = dynsm + BM * KPA;               // K * NPAD
    float* red_s = (float*)dynsm;                // alias (post-mainloop)
    float* red_d = red_s + BM * 2;

    const int tid  = threadIdx.x;
    const int lane = tid & 31, wid = tid >> 5;
    const int wm = wid & 3, wn = wid >> 2;
    const int r = lane >> 2, cq = lane & 3;
    const int row0 = blockIdx.y * BM;
    const int col0 = blockIdx.x * BN;

    const int aRow = lane & 15, aK = (lane >> 4) << 3;
    const int bK16 = lane & 15;
    const int bN8 = (lane >> 4) << 3;
    const unsigned aBase = (unsigned)__cvta_generic_to_shared(As);
    const unsigned bBase = (unsigned)__cvta_generic_to_shared(Bs);

    // ---- prologue: A via cp.async ----
    constexpr int AOPS = BM * K / 8;
#pragma unroll 4
    for (int i = tid; i < AOPS; i += 256) {
        const int row = i / (K / 8);
        const int kh = (i % (K / 8)) * 8;
        int srow = row0 + row;
        if (srow > M - 1) srow = M - 1;
        cp_async16(aBase + (unsigned)(row * KPA + kh) * 2,
                   Ah + (size_t)srow * K + kh);
    }
    asm volatile("cp.async.commit_group;" ::: "memory");

    // ---- prologue: B convert+stage ----
#pragma unroll 4
    for (int idx = tid; idx < K * (BN / 4); idx += 256) {
        const int k = idx / (BN / 4);
        const int n4 = (idx % (BN / 4)) * 4;
        float4 bv = *(const float4*)(Bg + (size_t)k * N + col0 + n4);
        __half2* p = (__half2*)&Bs[k * NPAD + n4];
        p[0] = __floats2half2_rn(bv.x, bv.y);
        p[1] = __floats2half2_rn(bv.z, bv.w);
    }
    asm volatile("cp.async.wait_group 0;" ::: "memory");
    __syncthreads();

    float acc[2][NTI][4];
#pragma unroll
    for (int mt = 0; mt < 2; mt++)
#pragma unroll
        for (int nt = 0; nt < NTI; nt++)
#pragma unroll
            for (int i = 0; i < 4; i++) acc[mt][nt][i] = 0.f;

    // ---- mainloop: straight-line, zero barriers ----
#pragma unroll
    for (int it = 0; it < NT; it++) {
        unsigned a[2][4], b[NTI][2];
#pragma unroll
        for (int mt = 0; mt < 2; mt++) {
            const int mb = wm * 32 + mt * 16;
            ldsm_x4(a[mt], aBase + (unsigned)((mb + aRow) * KPA + it * BK + aK) * 2);
        }
#pragma unroll
        for (int p = 0; p < NTI / 2; p++) {
            unsigned t[4];
            ldsm_x4_t(t, bBase + (unsigned)((it * BK + bK16) * NPAD + wn * WN + p * 16 + bN8) * 2);
            b[2 * p][0] = t[0]; b[2 * p][1] = t[1];
            b[2 * p + 1][0] = t[2]; b[2 * p + 1][1] = t[3];
        }
#pragma unroll
        for (int mt = 0; mt < 2; mt++)
#pragma unroll
            for (int nt = 0; nt < NTI; nt++)
                mma_f16(acc[mt][nt], a[mt], b[nt]);
    }

    // ---- epilogue: store fp16 C ----
#pragma unroll
    for (int mt = 0; mt < 2; mt++) {
        const int m_lo = row0 + wm * 32 + mt * 16 + r;
        const int m_hi = m_lo + 8;
#pragma unroll
        for (int nt = 0; nt < NTI; nt++) {
            const int n = col0 + wn * WN + nt * 8 + cq * 2;
            if (m_lo < M)
                *(__half2*)(C + (size_t)m_lo * N + n) =
                    __floats2half2_rn(acc[mt][nt][0], acc[mt][nt][1]);
            if (m_hi < M)
                *(__half2*)(C + (size_t)m_hi * N + n) =
                    __floats2half2_rn(acc[mt][nt][2], acc[mt][nt][3]);
        }
    }

    // ---- fused alpha epilogue (atomic-free; red aliases As) ----
    float ps0[2] = {0.f, 0.f}, ps1[2] = {0.f, 0.f};
    float pd0[2] = {0.f, 0.f}, pd1[2] = {0.f, 0.f};
#pragma unroll
    for (int nt = 0; nt < NTI; nt++) {
#pragma unroll
        for (int j = 0; j < 2; j++) {
            const int c = wn * WN + nt * 8 + cq * 2 + j;
            const float a_ = av[c], d_ = dv[c];
#pragma unroll
            for (int mt = 0; mt < 2; mt++) {
                ps0[mt] = fmaf(acc[mt][nt][j],     a_, ps0[mt]);
                pd0[mt] = fmaf(acc[mt][nt][j],     d_, pd0[mt]);
                ps1[mt] = fmaf(acc[mt][nt][2 + j], a_, ps1[mt]);
                pd1[mt] = fmaf(acc[mt][nt][2 + j], d_, pd1[mt]);
            }
        }
    }
#pragma unroll
    for (int o = 1; o <= 2; o <<= 1) {
#pragma unroll
        for (int mt = 0; mt < 2; mt++) {
            ps0[mt] += __shfl_xor_sync(0xffffffffu, ps0[mt], o);
            ps1[mt] += __shfl_xor_sync(0xffffffffu, ps1[mt], o);
            pd0[mt] += __shfl_xor_sync(0xffffffffu, pd0[mt], o);
            pd1[mt] += __shfl_xor_sync(0xffffffffu, pd1[mt], o);
        }
    }
    __syncthreads();
    if (cq == 0) {
#pragma unroll
        for (int mt = 0; mt < 2; mt++) {
            const int lr = wm * 32 + mt * 16 + r;
            red_s[lr * 2 + wn] = ps0[mt];
            red_s[(lr + 8) * 2 + wn] = ps1[mt];
            red_d[lr * 2 + wn] = pd0[mt];
            red_d[(lr + 8) * 2 + wn] = pd1[mt];
        }
    }
    __syncthreads();
    if (tid < BM) {
        const int row = row0 + tid;
        if (row < M) {
            if (NH == 2) {
                sOut[(size_t)row * SSTR]     = red_s[tid * 2];
                sOut[(size_t)row * SSTR + 1] = red_s[tid * 2 + 1];
                dOut[(size_t)row * SSTR]     = red_d[tid * 2];
                dOut[(size_t)row * SSTR + 1] = red_d[tid * 2 + 1];
            } else {
                sOut[row] = red_s[tid * 2] + red_s[tid * 2 + 1];
                dOut[row] = red_d[tid * 2] + red_d[tid * 2 + 1];
            }
        }
    }
}

#define SMEM_G1 ((128 * (INDIM + 8) + INDIM * (128 + 8)) * 2)   // 69632 B
#define SMEM_G2 ((128 * (D1 + 8) + D1 * (HD + 8)) * 2)          // 104448 B

__global__ void __launch_bounds__(256) k_gemm1(const float* __restrict__ B,
                                               const float* __restrict__ asrc,
                                               const float* __restrict__ adst) {
    mma_gemm<D1, INDIM, 128, 2, HEADS>(
        g_xh, B, g_h1h, NN,
        asrc + blockIdx.x * 128, adst + blockIdx.x * 128,
        g_as1 + blockIdx.x * 2, g_ad1 + blockIdx.x * 2);
}
__global__ void __launch_bounds__(256) k_gemm2(const float* __restrict__ B,
                                               const float* __restrict__ asrc,
                                               const float* __restrict__ adst) {
    mma_gemm<HD, D1, 64, 1, 1>(g_g1h, B, g_h2h, NN, asrc, adst, g_as2, g_ad2);
}

// ---------------- CSR build (counting sort by dst) ----------------
__global__ void k_hist(const int* __restrict__ dst) {
    int i = blockIdx.x * blockDim.x + threadIdx.x;
    if (i < EE) atomicAdd(&g_deg[dst[i]], 1);
}

#define SCAN_B 512
#define SCAN_NB ((NN + SCAN_B - 1) / SCAN_B)   // 196

__global__ void k_scan1() {
    __shared__ int sm[SCAN_B];
    int i = blockIdx.x * SCAN_B + threadIdx.x;
    int v = (i < NN) ? g_deg[i] + 1 : 0;       // +1 = self-loop
    sm[threadIdx.x] = v;
    __syncthreads();
    for (int off = 1; off < SCAN_B; off <<= 1) {
        int t = (threadIdx.x >= off) ? sm[threadIdx.x - off] : 0;
        __syncthreads();
        sm[threadIdx.x] += t;
        __syncthreads();
    }
    if (i < NN) g_rowptr[i] = sm[threadIdx.x] - v;
    if (threadIdx.x == SCAN_B - 1) g_blksums[blockIdx.x] = sm[threadIdx.x];
}
__global__ void k_scan3() {
    __shared__ int sm[256], sme[256];
    const int t = threadIdx.x;
    int v = (t < SCAN_NB) ? g_blksums[t] : 0;
    sm[t] = v;
    __syncthreads();
    for (int off = 1; off < 256; off <<= 1) {
        int x = (t >= off) ? sm[t - off] : 0;
        __syncthreads();
        sm[t] += x;
        __syncthreads();
    }
    sme[t] = sm[t] - v;                         // exclusive
    __syncthreads();
    int i = blockIdx.x * blockDim.x + t;
    if (i < NN) {
        int r = g_rowptr[i] + sme[i / SCAN_B];
        g_rowptr[i] = r;
        g_cursor[i] = r;
        g_deg[i] = 0;                           // re-zero for next launch's hist
    } else if (i == NN) {
        g_rowptr[NN] = ET;
    }
}
__global__ void k_scatter(const int* __restrict__ ei) {
    int i = blockIdx.x * blockDim.x + threadIdx.x;
    if (i >= ET) return;
    int s, d;
    if (i < EE) { s = ei[i]; d = ei[EE + i]; }
    else        { s = d = i - EE; }
    int pos = atomicAdd(&g_cursor[d], 1);
    g_srcs[pos] = s;
}

// ------- layer-1 aggregation: one warp per dst node, single pass -------
// srcs via __ldcs (streamed once), g1h store via __stcs: keep h1h L2-resident.
__global__ void __launch_bounds__(1024) k_agg1(const float* __restrict__ b1) {
    int gw = blockIdx.x * 32 + (threadIdx.x >> 5);
    if (gw >= NN) return;
    const int lane = threadIdx.x & 31;
    const int v = gw;
    const int r0 = g_rowptr[v], r1 = g_rowptr[v + 1];
    const float4 adv = ((const float4*)g_ad1)[v];

    const int head = lane >> 3;                // 8 lanes per head
    const float adh = head == 0 ? adv.x : head == 1 ? adv.y : head == 2 ? adv.z : adv.w;
    const float* asb = g_as1 + head;

    float S = 0.f;
    float acc[8];
#pragma unroll
    for (int i = 0; i < 8; i++) acc[i] = 0.f;

    const __half* h1b = g_h1h + lane * 8;
    int e = r0;
    for (; e + 4 <= r1; e += 4) {
        int sa = __ldcs(&g_srcs[e]),     sb = __ldcs(&g_srcs[e + 1]);
        int sc = __ldcs(&g_srcs[e + 2]), sd = __ldcs(&g_srcs[e + 3]);
        float wa = asb[sa * 4], wb = asb[sb * 4], wc = asb[sc * 4], wd = asb[sd * 4];
        uint4 ha = *(const uint4*)(h1b + (size_t)sa * D1);
        uint4 hb = *(const uint4*)(h1b + (size_t)sb * D1);
        uint4 hc = *(const uint4*)(h1b + (size_t)sc * D1);
        uint4 hd = *(const uint4*)(h1b + (size_t)sd * D1);
        float aa = __expf(lrelu(wa + adh) - SM_OFF);
        float ab = __expf(lrelu(wb + adh) - SM_OFF);
        float ac = __expf(lrelu(wc + adh) - SM_OFF);
        float ad = __expf(lrelu(wd + adh) - SM_OFF);
        S += (aa + ab) + (ac + ad);
        const __half2* pa = (const __half2*)&ha;
        const __half2* pb = (const __half2*)&hb;
        const __half2* pc = (const __half2*)&hc;
        const __half2* pd = (const __half2*)&hd;
#pragma unroll
        for (int j = 0; j < 4; j++) {
            float2 fa = __half22float2(pa[j]);
            float2 fb = __half22float2(pb[j]);
            float2 fc = __half22float2(pc[j]);
            float2 fd = __half22float2(pd[j]);
            acc[2 * j]     = fmaf(fa.x, aa, fmaf(fb.x, ab, fmaf(fc.x, ac, fmaf(fd.x, ad, acc[2 * j]))));
            acc[2 * j + 1] = fmaf(fa.y, aa, fmaf(fb.y, ab, fmaf(fc.y, ac, fmaf(fd.y, ad, acc[2 * j + 1]))));
        }
    }
    for (; e < r1; e++) {
        int s = __ldcs(&g_srcs[e]);
        float a = __expf(lrelu(asb[s * 4] + adh) - SM_OFF);
        S += a;
        uint4 hv = *(const uint4*)(h1b + (size_t)s * D1);
        const __half2* h2 = (const __half2*)&hv;
#pragma unroll
        for (int j = 0; j < 4; j++) {
            float2 f = __half22float2(h2[j]);
            acc[2 * j]     = fmaf(f.x, a, acc[2 * j]);
            acc[2 * j + 1] = fmaf(f.y, a, acc[2 * j + 1]);
        }
    }

    const float inv = 1.f / S;
    const float* bb = b1 + lane * 8;
    __half2 oh[4];
#pragma unroll
    for (int j = 0; j < 4; j++)
        oh[j] = __floats2half2_rn(eluf(fmaf(acc[2 * j], inv, bb[2 * j])),
                                  eluf(fmaf(acc[2 * j + 1], inv, bb[2 * j + 1])));
    uint4* op = (uint4*)(g_g1h + (size_t)v * D1 + lane * 8);
    __stcs(op, *(uint4*)oh);
}

// ------- layer-2 aggregation + ELU + final linear, single pass -------
__global__ void __launch_bounds__(1024) k_agg2(const float* __restrict__ b2,
                                               const float* __restrict__ lw,
                                               const float* __restrict__ lb,
                                               float* __restrict__ out) {
    int gw = blockIdx.x * 32 + (threadIdx.x >> 5);
    if (gw >= NN) return;
    const int lane = threadIdx.x & 31;
    const int v = gw;
    const int r0 = g_rowptr[v], r1 = g_rowptr[v + 1];
    const float adv = g_ad2[v];

    float S = 0.f;
    float2 acc = make_float2(0.f, 0.f);
    const __half* h2b = g_h2h + lane * 2;
    int e = r0;
    for (; e + 4 <= r1; e += 4) {
        int sa = __ldcs(&g_srcs[e]),     sb = __ldcs(&g_srcs[e + 1]);
        int sc = __ldcs(&g_srcs[e + 2]), sd = __ldcs(&g_srcs[e + 3]);
        float wa = g_as2[sa], wb = g_as2[sb], wc = g_as2[sc], wd = g_as2[sd];
        __half2 xa = *(const __half2*)(h2b + (size_t)sa * HD);
        __half2 xb = *(const __half2*)(h2b + (size_t)sb * HD);
        __half2 xc = *(const __half2*)(h2b + (size_t)sc * HD);
        __half2 xd = *(const __half2*)(h2b + (size_t)sd * HD);
        float aa = __expf(lrelu(wa + adv) - SM_OFF);
        float ab = __expf(lrelu(wb + adv) - SM_OFF);
        float ac = __expf(lrelu(wc + adv) - SM_OFF);
        float ad = __expf(lrelu(wd + adv) - SM_OFF);
        S += (aa + ab) + (ac + ad);
        float2 fa = __half22float2(xa), fb = __half22float2(xb);
        float2 fc = __half22float2(xc), fd = __half22float2(xd);
        acc.x = fmaf(fa.x, aa, fmaf(fb.x, ab, fmaf(fc.x, ac, fmaf(fd.x, ad, acc.x))));
        acc.y = fmaf(fa.y, aa, fmaf(fb.y, ab, fmaf(fc.y, ac, fmaf(fd.y, ad, acc.y))));
    }
    for (; e < r1; e++) {
        int s = __ldcs(&g_srcs[e]);
        float a = __expf(lrelu(g_as2[s] + adv) - SM_OFF);
        S += a;
        float2 x = __half22float2(*(const __half2*)(h2b + (size_t)s * HD));
        acc.x = fmaf(x.x, a, acc.x);
        acc.y = fmaf(x.y, a, acc.y);
    }

    const float inv = 1.f / S;
    const int d = 2 * lane;
    float t0 = eluf(fmaf(acc.x, inv, b2[d]));
    float t1 = eluf(fmaf(acc.y, inv, b2[d + 1]));
    float y0 = t0 * lw[d * 2]     + t1 * lw[d * 2 + 2];
    float y1 = t0 * lw[d * 2 + 1] + t1 * lw[d * 2 + 3];
#pragma unroll
    for (int o = 16; o; o >>= 1) {
        y0 += __shfl_xor_sync(0xffffffffu, y0, o);
        y1 += __shfl_xor_sync(0xffffffffu, y1, o);
    }
    if (lane == 0) {
        out[2 * v]     = y0 + lb[0];
        out[2 * v + 1] = y1 + lb[1];
    }
}

// ---------------- launch ----------------
extern "C" void kernel_launch(void* const* d_in, const int* in_sizes, int n_in,
                              void* d_out, int out_size) {
    const float* x      = (const float*)d_in[0];
    const int*   ei     = (const int*)d_in[1];     // int32: jax default x64 disabled
    const float* W1     = (const float*)d_in[2];
    const float* a_src1 = (const float*)d_in[3];
    const float* a_dst1 = (const float*)d_in[4];
    const float* b1     = (const float*)d_in[5];
    const float* W2     = (const float*)d_in[6];
    const float* a_src2 = (const float*)d_in[7];
    const float* a_dst2 = (const float*)d_in[8];
    const float* b2     = (const float*)d_in[9];
    const float* lw     = (const float*)d_in[10];
    const float* lb     = (const float*)d_in[11];
    float*       out    = (float*)d_out;

    static cudaStream_t s1 = nullptr;
    static cudaEvent_t evRoot = nullptr, evCsr = nullptr;
    if (s1 == nullptr) {
        cudaStreamCreateWithFlags(&s1, cudaStreamNonBlocking);
        cudaEventCreateWithFlags(&evRoot, cudaEventDisableTiming);
        cudaEventCreateWithFlags(&evCsr, cudaEventDisableTiming);
        cudaFuncSetAttribute(k_gemm1, cudaFuncAttributeMaxDynamicSharedMemorySize, SMEM_G1);
        cudaFuncSetAttribute(k_gemm2, cudaFuncAttributeMaxDynamicSharedMemorySize, SMEM_G2);
    }

    // fork: CSR chain on s1, x-convert + GEMM1 on main stream
    cudaEventRecord(evRoot, 0);
    cudaStreamWaitEvent(s1, evRoot, 0);

    k_xh<<<(NN * INDIM / 8 + 255) / 256, 256>>>(x);             // #1 (main)
    k_hist<<<(EE + 255) / 256, 256, 0, s1>>>(ei + EE);          // #2
    k_scan1<<<SCAN_NB, SCAN_B, 0, s1>>>();                      // #3

    k_gemm1<<<dim3(2, (NN + 127) / 128), 256, SMEM_G1>>>(W1, a_src1, a_dst1);  // #4 (profiled)

    k_scan3<<<(NN + 1 + 255) / 256, 256, 0, s1>>>();            // #5
    k_scatter<<<(ET + 255) / 256, 256, 0, s1>>>(ei);            // #6
    cudaEventRecord(evCsr, s1);

    // join: agg1 needs CSR + gemm1(+fused alphas)
    cudaStreamWaitEvent(0, evCsr, 0);
    k_agg1<<<(NN + 31) / 32, 1024>>>(b1);                       // #7

    // layer 2
    k_gemm2<<<dim3(1, (NN + 127) / 128), 256, SMEM_G2>>>(W2, a_src2, a_dst2);  // #8
    k_agg2<<<(NN + 31) / 32, 1024>>>(b2, lw, lb, out);          // #9
}

// round 16
// speedup vs baseline: 1.0199x; 1.0199x over previous
#include <cuda_runtime.h>
#include <cuda_fp16.h>
#include <cstdint>

#define NN 100000
#define EE 3200000
#define ET (EE + NN)           // 3,300,000 edges incl. self loops
#define HEADS 4
#define HD 64
#define D1 256                 // HEADS*HD
#define INDIM 128

// ---------------- scratch (static device globals; no allocs) ----------------
__device__ __half g_xh[(size_t)NN * INDIM]; // x (fp16)                   (25.6 MB)
__device__ __half g_h1h[(size_t)NN * D1];   // layer1 h (fp16)            (51.2 MB)
__device__ __half g_g1h[(size_t)NN * D1];   // elu(agg1+b1) (fp16)        (51.2 MB)
__device__ __half g_h2h[(size_t)NN * HD];   // layer2 h (fp16)            (12.8 MB)
__device__ float g_as1[NN * HEADS];
__device__ float g_ad1[NN * HEADS];
__device__ float g_as2[NN];
__device__ float g_ad2[NN];
__device__ int   g_deg[NN];                 // zero at entry of every launch
__device__ int   g_rowptr[NN + 1];
__device__ int   g_cursor[NN];
__device__ int   g_blksums[256];
__device__ int   g_srcs[ET];                // CSR-by-dst src indices (13.2 MB)

__device__ __forceinline__ float lrelu(float x) { return fmaxf(x, 0.2f * x); }
__device__ __forceinline__ float eluf(float x)  { return x > 0.f ? x : expm1f(x); }

#define SM_OFF 8.0f   // constant softmax offset (exact in ratio; avoids overflow)

__device__ __forceinline__ void mma_f16(float* d, const unsigned* a, const unsigned* b) {
    asm volatile(
        "mma.sync.aligned.m16n8k16.row.col.f32.f16.f16.f32 "
        "{%0,%1,%2,%3}, {%4,%5,%6,%7}, {%8,%9}, {%0,%1,%2,%3};\n"
        : "+f"(d[0]), "+f"(d[1]), "+f"(d[2]), "+f"(d[3])
        : "r"(a[0]), "r"(a[1]), "r"(a[2]), "r"(a[3]), "r"(b[0]), "r"(b[1]));
}

__device__ __forceinline__ void ldsm_x4(unsigned* r, unsigned addr) {
    asm volatile("ldmatrix.sync.aligned.m8n8.x4.shared.b16 {%0,%1,%2,%3}, [%4];"
                 : "=r"(r[0]), "=r"(r[1]), "=r"(r[2]), "=r"(r[3]) : "r"(addr));
}
__device__ __forceinline__ void ldsm_x4_t(unsigned* r, unsigned addr) {
    asm volatile("ldmatrix.sync.aligned.m8n8.x4.trans.shared.b16 {%0,%1,%2,%3}, [%4];"
                 : "=r"(r[0]), "=r"(r[1]), "=r"(r[2]), "=r"(r[3]) : "r"(addr));
}
__device__ __forceinline__ void cp_async16(unsigned dst, const void* src) {
    asm volatile("cp.async.cg.shared.global [%0], [%1], 16;" :: "r"(dst), "l"(src));
}

// ---------------- x -> fp16 pre-convert ----------------
__global__ void k_xh(const float* __restrict__ x) {
    int i = blockIdx.x * blockDim.x + threadIdx.x;   // 8 elems per thread
    if (i >= NN * INDIM / 8) return;
    const float4* p = (const float4*)x + (size_t)i * 2;
    float4 f0 = p[0], f1 = p[1];
    __half2 h[4];
    h[0] = __floats2half2_rn(f0.x, f0.y);
    h[1] = __floats2half2_rn(f0.z, f0.w);
    h[2] = __floats2half2_rn(f1.x, f1.y);
    h[3] = __floats2half2_rn(f1.z, f1.w);
    *(uint4*)(g_xh + (size_t)i * 8) = *(uint4*)h;
}

// ------- fp16 tensor-core GEMM, K-chunked staging, zero-sync inner loop -----
// KC: K-chunk held in smem. gemm1: KC=K (one chunk, unchanged path).
// gemm2: KC=128 -> smem 52KB -> 2 CTAs/SM (prologue of one hides behind
// mainloop of the other). Accumulators persist across chunks (same tile order
// as unchunked => identical arithmetic).
template<int N, int K, int BN, int NH, int SSTR, int KC>
__device__ __forceinline__ void mma_gemm(const __half* __restrict__ Ah,
                                         const float* __restrict__ Bg,
                                         __half* __restrict__ C, int M,
                                         const float* __restrict__ av,
                                         const float* __restrict__ dv,
                                         float* __restrict__ sOut,
                                         float* __restrict__ dOut) {
    constexpr int BM = 128, BK = 16;
    constexpr int WN = BN / 2;
    constexpr int NTI = WN / 8;
    constexpr int KPA = KC + 8;
    constexpr int NPAD = BN + 8;
    constexpr int NTC = KC / BK;      // tiles per chunk
    constexpr int NCH = K / KC;       // chunks

    extern __shared__ __align__(16) __half dynsm[];
    __half* As = dynsm;                          // BM * KPA
    __half* Bs = dynsm + BM * KPA;               // KC * NPAD
    float* red_s = (float*)dynsm;                // alias (post-mainloop)
    float* red_d = red_s + BM * 2;

    const int tid  = threadIdx.x;
    const int lane = tid & 31, wid = tid >> 5;
    const int wm = wid & 3, wn = wid >> 2;
    const int r = lane >> 2, cq = lane & 3;
    const int row0 = blockIdx.y * BM;
    const int col0 = blockIdx.x * BN;

    const int aRow = lane & 15, aK = (lane >> 4) << 3;
    const int bK16 = lane & 15;
    const int bN8 = (lane >> 4) << 3;
    const unsigned aBase = (unsigned)__cvta_generic_to_shared(As);
    const unsigned bBase = (unsigned)__cvta_generic_to_shared(Bs);

    float acc[2][NTI][4];
#pragma unroll
    for (int mt = 0; mt < 2; mt++)
#pragma unroll
        for (int nt = 0; nt < NTI; nt++)
#pragma unroll
            for (int i = 0; i < 4; i++) acc[mt][nt][i] = 0.f;

#pragma unroll 1
    for (int ch = 0; ch < NCH; ch++) {
        const int kc0 = ch * KC;

        // ---- stage A chunk via cp.async ----
        constexpr int AOPS = BM * KC / 8;
#pragma unroll 4
        for (int i = tid; i < AOPS; i += 256) {
            const int row = i / (KC / 8);
            const int kh = (i % (KC / 8)) * 8;
            int srow = row0 + row;
            if (srow > M - 1) srow = M - 1;      // clamp: safe, discarded
            cp_async16(aBase + (unsigned)(row * KPA + kh) * 2,
                       Ah + (size_t)srow * K + kc0 + kh);
        }
        asm volatile("cp.async.commit_group;" ::: "memory");

        // ---- stage B chunk ([k][n], vectorized, conflict-free) ----
#pragma unroll 4
        for (int idx = tid; idx < KC * (BN / 4); idx += 256) {
            const int k = idx / (BN / 4);
            const int n4 = (idx % (BN / 4)) * 4;
            float4 bv = *(const float4*)(Bg + (size_t)(kc0 + k) * N + col0 + n4);
            __half2* p = (__half2*)&Bs[k * NPAD + n4];
            p[0] = __floats2half2_rn(bv.x, bv.y);
            p[1] = __floats2half2_rn(bv.z, bv.w);
        }
        asm volatile("cp.async.wait_group 0;" ::: "memory");
        __syncthreads();

        // ---- chunk mainloop: straight-line, zero barriers ----
#pragma unroll
        for (int it = 0; it < NTC; it++) {
            unsigned a[2][4], b[NTI][2];
#pragma unroll
            for (int mt = 0; mt < 2; mt++) {
                const int mb = wm * 32 + mt * 16;
                ldsm_x4(a[mt], aBase + (unsigned)((mb + aRow) * KPA + it * BK + aK) * 2);
            }
#pragma unroll
            for (int p = 0; p < NTI / 2; p++) {
                unsigned t[4];
                ldsm_x4_t(t, bBase + (unsigned)((it * BK + bK16) * NPAD + wn * WN + p * 16 + bN8) * 2);
                b[2 * p][0] = t[0]; b[2 * p][1] = t[1];
                b[2 * p + 1][0] = t[2]; b[2 * p + 1][1] = t[3];
            }
#pragma unroll
            for (int mt = 0; mt < 2; mt++)
#pragma unroll
                for (int nt = 0; nt < NTI; nt++)
                    mma_f16(acc[mt][nt], a[mt], b[nt]);
        }

        if (ch + 1 < NCH) __syncthreads();       // all reads done before restage
    }

    // ---- epilogue: store fp16 C ----
#pragma unroll
    for (int mt = 0; mt < 2; mt++) {
        const int m_lo = row0 + wm * 32 + mt * 16 + r;
        const int m_hi = m_lo + 8;
#pragma unroll
        for (int nt = 0; nt < NTI; nt++) {
            const int n = col0 + wn * WN + nt * 8 + cq * 2;
            if (m_lo < M)
                *(__half2*)(C + (size_t)m_lo * N + n) =
                    __floats2half2_rn(acc[mt][nt][0], acc[mt][nt][1]);
            if (m_hi < M)
                *(__half2*)(C + (size_t)m_hi * N + n) =
                    __floats2half2_rn(acc[mt][nt][2], acc[mt][nt][3]);
        }
    }

    // ---- fused alpha epilogue (atomic-free; red aliases As) ----
    float ps0[2] = {0.f, 0.f}, ps1[2] = {0.f, 0.f};
    float pd0[2] = {0.f, 0.f}, pd1[2] = {0.f, 0.f};
#pragma unroll
    for (int nt = 0; nt < NTI; nt++) {
#pragma unroll
        for (int j = 0; j < 2; j++) {
            const int c = wn * WN + nt * 8 + cq * 2 + j;
            const float a_ = av[c], d_ = dv[c];
#pragma unroll
            for (int mt = 0; mt < 2; mt++) {
                ps0[mt] = fmaf(acc[mt][nt][j],     a_, ps0[mt]);
                pd0[mt] = fmaf(acc[mt][nt][j],     d_, pd0[mt]);
                ps1[mt] = fmaf(acc[mt][nt][2 + j], a_, ps1[mt]);
                pd1[mt] = fmaf(acc[mt][nt][2 + j], d_, pd1[mt]);
            }
        }
    }
#pragma unroll
    for (int o = 1; o <= 2; o <<= 1) {
#pragma unroll
        for (int mt = 0; mt < 2; mt++) {
            ps0[mt] += __shfl_xor_sync(0xffffffffu, ps0[mt], o);
            ps1[mt] += __shfl_xor_sync(0xffffffffu, ps1[mt], o);
            pd0[mt] += __shfl_xor_sync(0xffffffffu, pd0[mt], o);
            pd1[mt] += __shfl_xor_sync(0xffffffffu, pd1[mt], o);
        }
    }
    __syncthreads();
    if (cq == 0) {
#pragma unroll
        for (int mt = 0; mt < 2; mt++) {
            const int lr = wm * 32 + mt * 16 + r;
            red_s[lr * 2 + wn] = ps0[mt];
            red_s[(lr + 8) * 2 + wn] = ps1[mt];
            red_d[lr * 2 + wn] = pd0[mt];
            red_d[(lr + 8) * 2 + wn] = pd1[mt];
        }
    }
    __syncthreads();
    if (tid < BM) {
        const int row = row0 + tid;
        if (row < M) {
            if (NH == 2) {
                sOut[(size_t)row * SSTR]     = red_s[tid * 2];
                sOut[(size_t)row * SSTR + 1] = red_s[tid * 2 + 1];
                dOut[(size_t)row * SSTR]     = red_d[tid * 2];
                dOut[(size_t)row * SSTR + 1] = red_d[tid * 2 + 1];
            } else {
                sOut[row] = red_s[tid * 2] + red_s[tid * 2 + 1];
                dOut[row] = red_d[tid * 2] + red_d[tid * 2 + 1];
            }
        }
    }
}

#define SMEM_G1 ((128 * (INDIM + 8) + INDIM * (128 + 8)) * 2)   // 69632 B
#define SMEM_G2 ((128 * (128 + 8) + 128 * (HD + 8)) * 2)        // 53248 B -> 2 CTA/SM

__global__ void __launch_bounds__(256) k_gemm1(const float* __restrict__ B,
                                               const float* __restrict__ asrc,
                                               const float* __restrict__ adst) {
    mma_gemm<D1, INDIM, 128, 2, HEADS, INDIM>(
        g_xh, B, g_h1h, NN,
        asrc + blockIdx.x * 128, adst + blockIdx.x * 128,
        g_as1 + blockIdx.x * 2, g_ad1 + blockIdx.x * 2);
}
__global__ void __launch_bounds__(256) k_gemm2(const float* __restrict__ B,
                                               const float* __restrict__ asrc,
                                               const float* __restrict__ adst) {
    mma_gemm<HD, D1, 64, 1, 1, 128>(g_g1h, B, g_h2h, NN, asrc, adst, g_as2, g_ad2);
}

// ---------------- CSR build (counting sort by dst) ----------------
__global__ void k_hist(const int* __restrict__ dst) {
    int i = blockIdx.x * blockDim.x + threadIdx.x;
    if (i < EE) atomicAdd(&g_deg[dst[i]], 1);
}

#define SCAN_B 512
#define SCAN_NB ((NN + SCAN_B - 1) / SCAN_B)   // 196

__global__ void k_scan1() {
    __shared__ int sm[SCAN_B];
    int i = blockIdx.x * SCAN_B + threadIdx.x;
    int v = (i < NN) ? g_deg[i] + 1 : 0;       // +1 = self-loop
    sm[threadIdx.x] = v;
    __syncthreads();
    for (int off = 1; off < SCAN_B; off <<= 1) {
        int t = (threadIdx.x >= off) ? sm[threadIdx.x - off] : 0;
        __syncthreads();
        sm[threadIdx.x] += t;
        __syncthreads();
    }
    if (i < NN) g_rowptr[i] = sm[threadIdx.x] - v;
    if (threadIdx.x == SCAN_B - 1) g_blksums[blockIdx.x] = sm[threadIdx.x];
}
__global__ void k_scan3() {
    __shared__ int sm[256], sme[256];
    const int t = threadIdx.x;
    int v = (t < SCAN_NB) ? g_blksums[t] : 0;
    sm[t] = v;
    __syncthreads();
    for (int off = 1; off < 256; off <<= 1) {
        int x = (t >= off) ? sm[t - off] : 0;
        __syncthreads();
        sm[t] += x;
        __syncthreads();
    }
    sme[t] = sm[t] - v;                         // exclusive
    __syncthreads();
    int i = blockIdx.x * blockDim.x + t;
    if (i < NN) {
        int r = g_rowptr[i] + sme[i / SCAN_B];
        g_rowptr[i] = r;
        g_cursor[i] = r;
        g_deg[i] = 0;                           // re-zero for next launch's hist
    } else if (i == NN) {
        g_rowptr[NN] = ET;
    }
}
__global__ void k_scatter(const int* __restrict__ ei) {
    int i = blockIdx.x * blockDim.x + threadIdx.x;
    if (i >= ET) return;
    int s, d;
    if (i < EE) { s = ei[i]; d = ei[EE + i]; }
    else        { s = d = i - EE; }
    int pos = atomicAdd(&g_cursor[d], 1);
    g_srcs[pos] = s;
}

// ------- layer-1 aggregation: one warp per dst node, single pass -------
__global__ void __launch_bounds__(1024) k_agg1(const float* __restrict__ b1) {
    int gw = blockIdx.x * 32 + (threadIdx.x >> 5);
    if (gw >= NN) return;
    const int lane = threadIdx.x & 31;
    const int v = gw;
    const int r0 = g_rowptr[v], r1 = g_rowptr[v + 1];
    const float4 adv = ((const float4*)g_ad1)[v];

    const int head = lane >> 3;                // 8 lanes per head
    const float adh = head == 0 ? adv.x : head == 1 ? adv.y : head == 2 ? adv.z : adv.w;
    const float* asb = g_as1 + head;

    float S = 0.f;
    float acc[8];
#pragma unroll
    for (int i = 0; i < 8; i++) acc[i] = 0.f;

    const __half* h1b = g_h1h + lane * 8;
    int e = r0;
    for (; e + 4 <= r1; e += 4) {
        int sa = g_srcs[e], sb = g_srcs[e + 1], sc = g_srcs[e + 2], sd = g_srcs[e + 3];
        float wa = asb[sa * 4], wb = asb[sb * 4], wc = asb[sc * 4], wd = asb[sd * 4];
        uint4 ha = *(const uint4*)(h1b + (size_t)sa * D1);
        uint4 hb = *(const uint4*)(h1b + (size_t)sb * D1);
        uint4 hc = *(const uint4*)(h1b + (size_t)sc * D1);
        uint4 hd = *(const uint4*)(h1b + (size_t)sd * D1);
        float aa = __expf(lrelu(wa + adh) - SM_OFF);
        float ab = __expf(lrelu(wb + adh) - SM_OFF);
        float ac = __expf(lrelu(wc + adh) - SM_OFF);
        float ad = __expf(lrelu(wd + adh) - SM_OFF);
        S += (aa + ab) + (ac + ad);
        const __half2* pa = (const __half2*)&ha;
        const __half2* pb = (const __half2*)&hb;
        const __half2* pc = (const __half2*)&hc;
        const __half2* pd = (const __half2*)&hd;
#pragma unroll
        for (int j = 0; j < 4; j++) {
            float2 fa = __half22float2(pa[j]);
            float2 fb = __half22float2(pb[j]);
            float2 fc = __half22float2(pc[j]);
            float2 fd = __half22float2(pd[j]);
            acc[2 * j]     = fmaf(fa.x, aa, fmaf(fb.x, ab, fmaf(fc.x, ac, fmaf(fd.x, ad, acc[2 * j]))));
            acc[2 * j + 1] = fmaf(fa.y, aa, fmaf(fb.y, ab, fmaf(fc.y, ac, fmaf(fd.y, ad, acc[2 * j + 1]))));
        }
    }
    for (; e < r1; e++) {
        int s = g_srcs[e];
        float a = __expf(lrelu(asb[s * 4] + adh) - SM_OFF);
        S += a;
        uint4 hv = *(const uint4*)(h1b + (size_t)s * D1);
        const __half2* h2 = (const __half2*)&hv;
#pragma unroll
        for (int j = 0; j < 4; j++) {
            float2 f = __half22float2(h2[j]);
            acc[2 * j]     = fmaf(f.x, a, acc[2 * j]);
            acc[2 * j + 1] = fmaf(f.y, a, acc[2 * j + 1]);
        }
    }

    const float inv = 1.f / S;
    const float* bb = b1 + lane * 8;
    __half2 oh[4];
#pragma unroll
    for (int j = 0; j < 4; j++)
        oh[j] = __floats2half2_rn(eluf(fmaf(acc[2 * j], inv, bb[2 * j])),
                                  eluf(fmaf(acc[2 * j + 1], inv, bb[2 * j + 1])));
    *(uint4*)(g_g1h + (size_t)v * D1 + lane * 8) = *(uint4*)oh;
}

// ------- layer-2 aggregation + ELU + final linear, single pass -------
__global__ void __launch_bounds__(1024) k_agg2(const float* __restrict__ b2,
                                               const float* __restrict__ lw,
                                               const float* __restrict__ lb,
                                               float* __restrict__ out) {
    int gw = blockIdx.x * 32 + (threadIdx.x >> 5);
    if (gw >= NN) return;
    const int lane = threadIdx.x & 31;
    const int v = gw;
    const int r0 = g_rowptr[v], r1 = g_rowptr[v + 1];
    const float adv = g_ad2[v];

    float S = 0.f;
    float2 acc = make_float2(0.f, 0.f);
    const __half* h2b = g_h2h + lane * 2;
    int e = r0;
    for (; e + 4 <= r1; e += 4) {
        int sa = g_srcs[e], sb = g_srcs[e + 1], sc = g_srcs[e + 2], sd = g_srcs[e + 3];
        float wa = g_as2[sa], wb = g_as2[sb], wc = g_as2[sc], wd = g_as2[sd];
        __half2 xa = *(const __half2*)(h2b + (size_t)sa * HD);
        __half2 xb = *(const __half2*)(h2b + (size_t)sb * HD);
        __half2 xc = *(const __half2*)(h2b + (size_t)sc * HD);
        __half2 xd = *(const __half2*)(h2b + (size_t)sd * HD);
        float aa = __expf(lrelu(wa + adv) - SM_OFF);
        float ab = __expf(lrelu(wb + adv) - SM_OFF);
        float ac = __expf(lrelu(wc + adv) - SM_OFF);
        float ad = __expf(lrelu(wd + adv) - SM_OFF);
        S += (aa + ab) + (ac + ad);
        float2 fa = __half22float2(xa), fb = __half22float2(xb);
        float2 fc = __half22float2(xc), fd = __half22float2(xd);
        acc.x = fmaf(fa.x, aa, fmaf(fb.x, ab, fmaf(fc.x, ac, fmaf(fd.x, ad, acc.x))));
        acc.y = fmaf(fa.y, aa, fmaf(fb.y, ab, fmaf(fc.y, ac, fmaf(fd.y, ad, acc.y))));
    }
    for (; e < r1; e++) {
        int s = g_srcs[e];
        float a = __expf(lrelu(g_as2[s] + adv) - SM_OFF);
        S += a;
        float2 x = __half22float2(*(const __half2*)(h2b + (size_t)s * HD));
        acc.x = fmaf(x.x, a, acc.x);
        acc.y = fmaf(x.y, a, acc.y);
    }

    const float inv = 1.f / S;
    const int d = 2 * lane;
    float t0 = eluf(fmaf(acc.x, inv, b2[d]));
    float t1 = eluf(fmaf(acc.y, inv, b2[d + 1]));
    float y0 = t0 * lw[d * 2]     + t1 * lw[d * 2 + 2];
    float y1 = t0 * lw[d * 2 + 1] + t1 * lw[d * 2 + 3];
#pragma unroll
    for (int o = 16; o; o >>= 1) {
        y0 += __shfl_xor_sync(0xffffffffu, y0, o);
        y1 += __shfl_xor_sync(0xffffffffu, y1, o);
    }
    if (lane == 0) {
        out[2 * v]     = y0 + lb[0];
        out[2 * v + 1] = y1 + lb[1];
    }
}

// ---------------- launch ----------------
extern "C" void kernel_launch(void* const* d_in, const int* in_sizes, int n_in,
                              void* d_out, int out_size) {
    const float* x      = (const float*)d_in[0];
    const int*   ei     = (const int*)d_in[1];     // int32: jax default x64 disabled
    const float* W1     = (const float*)d_in[2];
    const float* a_src1 = (const float*)d_in[3];
    const float* a_dst1 = (const float*)d_in[4];
    const float* b1     = (const float*)d_in[5];
    const float* W2     = (const float*)d_in[6];
    const float* a_src2 = (const float*)d_in[7];
    const float* a_dst2 = (const float*)d_in[8];
    const float* b2     = (const float*)d_in[9];
    const float* lw     = (const float*)d_in[10];
    const float* lb     = (const float*)d_in[11];
    float*       out    = (float*)d_out;

    static cudaStream_t s1 = nullptr;
    static cudaEvent_t evRoot = nullptr, evCsr = nullptr;
    if (s1 == nullptr) {
        cudaStreamCreateWithFlags(&s1, cudaStreamNonBlocking);
        cudaEventCreateWithFlags(&evRoot, cudaEventDisableTiming);
        cudaEventCreateWithFlags(&evCsr, cudaEventDisableTiming);
        cudaFuncSetAttribute(k_gemm1, cudaFuncAttributeMaxDynamicSharedMemorySize, SMEM_G1);
        cudaFuncSetAttribute(k_gemm2, cudaFuncAttributeMaxDynamicSharedMemorySize, SMEM_G2);
    }

    // fork: CSR chain on s1, x-convert + GEMM1 on main stream
    cudaEventRecord(evRoot, 0);
    cudaStreamWaitEvent(s1, evRoot, 0);

    k_xh<<<(NN * INDIM / 8 + 255) / 256, 256>>>(x);             // #1 (main)
    k_hist<<<(EE + 255) / 256, 256, 0, s1>>>(ei + EE);          // #2
    k_scan1<<<SCAN_NB, SCAN_B, 0, s1>>>();                      // #3

    k_gemm1<<<dim3(2, (NN + 127) / 128), 256, SMEM_G1>>>(W1, a_src1, a_dst1);  // #4 (profiled)

    k_scan3<<<(NN + 1 + 255) / 256, 256, 0, s1>>>();            // #5
    k_scatter<<<(ET + 255) / 256, 256, 0, s1>>>(ei);            // #6
    cudaEventRecord(evCsr, s1);

    // join: agg1 needs CSR + gemm1(+fused alphas)
    cudaStreamWaitEvent(0, evCsr, 0);
    k_agg1<<<(NN + 31) / 32, 1024>>>(b1);                       // #7

    // layer 2
    k_gemm2<<<dim3(1, (NN + 127) / 128), 256, SMEM_G2>>>(W2, a_src2, a_dst2);  // #8
    k_agg2<<<(NN + 31) / 32, 1024>>>(b2, lw, lb, out);          // #9
}

// round 17
// speedup vs baseline: 1.0204x; 1.0005x over previous
#include <cuda_runtime.h>
#include <cuda_fp16.h>
#include <cstdint>

#define NN 100000
#define EE 3200000
#define ET (EE + NN)           // 3,300,000 edges incl. self loops
#define HEADS 4
#define HD 64
#define D1 256                 // HEADS*HD
#define INDIM 128

// ---------------- scratch (static device globals; no allocs) ----------------
__device__ __half g_h1h[(size_t)NN * D1];   // layer1 h (fp16)            (51.2 MB)
__device__ __half g_g1h[(size_t)NN * D1];   // elu(agg1+b1) (fp16)        (51.2 MB)
__device__ __half g_h2h[(size_t)NN * HD];   // layer2 h (fp16)            (12.8 MB)
__device__ float g_as1[NN * HEADS];
__device__ float g_ad1[NN * HEADS];
__device__ float g_as2[NN];
__device__ float g_ad2[NN];
__device__ int   g_deg[NN];                 // zero at entry of every launch
__device__ int   g_rowptr[NN + 1];
__device__ int   g_cursor[NN];
__device__ int   g_blksums[256];
__device__ int   g_srcs[ET];                // CSR-by-dst src indices (13.2 MB)

__device__ __forceinline__ float lrelu(float x) { return fmaxf(x, 0.2f * x); }
__device__ __forceinline__ float eluf(float x)  { return x > 0.f ? x : expm1f(x); }

#define SM_OFF 8.0f   // constant softmax offset (exact in ratio; avoids overflow)

__device__ __forceinline__ void mma_f16(float* d, const unsigned* a, const unsigned* b) {
    asm volatile(
        "mma.sync.aligned.m16n8k16.row.col.f32.f16.f16.f32 "
        "{%0,%1,%2,%3}, {%4,%5,%6,%7}, {%8,%9}, {%0,%1,%2,%3};\n"
        : "+f"(d[0]), "+f"(d[1]), "+f"(d[2]), "+f"(d[3])
        : "r"(a[0]), "r"(a[1]), "r"(a[2]), "r"(a[3]), "r"(b[0]), "r"(b[1]));
}

__device__ __forceinline__ void ldsm_x4(unsigned* r, unsigned addr) {
    asm volatile("ldmatrix.sync.aligned.m8n8.x4.shared.b16 {%0,%1,%2,%3}, [%4];"
                 : "=r"(r[0]), "=r"(r[1]), "=r"(r[2]), "=r"(r[3]) : "r"(addr));
}
__device__ __forceinline__ void ldsm_x4_t(unsigned* r, unsigned addr) {
    asm volatile("ldmatrix.sync.aligned.m8n8.x4.trans.shared.b16 {%0,%1,%2,%3}, [%4];"
                 : "=r"(r[0]), "=r"(r[1]), "=r"(r[2]), "=r"(r[3]) : "r"(addr));
}
__device__ __forceinline__ void cp_async16(unsigned dst, const void* src) {
    asm volatile("cp.async.cg.shared.global [%0], [%1], 16;" :: "r"(dst), "l"(src));
}

// ------- fp16 tensor-core GEMM, K-chunked staging, zero-sync inner loop -----
// AHALF: A already fp16 in gmem (cp.async path). Else A is fp32 and is
// converted at staging (identical rounding to a separate pre-convert pass).
// gemm1: KC=K (one chunk). gemm2: KC=128 -> 52KB smem -> 2 CTAs/SM.
template<int N, int K, bool AHALF, int BN, int NH, int SSTR, int KC>
__device__ __forceinline__ void mma_gemm(const void* __restrict__ Av,
                                         const float* __restrict__ Bg,
                                         __half* __restrict__ C, int M,
                                         const float* __restrict__ av,
                                         const float* __restrict__ dv,
                                         float* __restrict__ sOut,
                                         float* __restrict__ dOut) {
    constexpr int BM = 128, BK = 16;
    constexpr int WN = BN / 2;
    constexpr int NTI = WN / 8;
    constexpr int KPA = KC + 8;
    constexpr int NPAD = BN + 8;
    constexpr int NTC = KC / BK;      // tiles per chunk
    constexpr int NCH = K / KC;       // chunks

    extern __shared__ __align__(16) __half dynsm[];
    __half* As = dynsm;                          // BM * KPA
    __half* Bs = dynsm + BM * KPA;               // KC * NPAD
    float* red_s = (float*)dynsm;                // alias (post-mainloop)
    float* red_d = red_s + BM * 2;

    const int tid  = threadIdx.x;
    const int lane = tid & 31, wid = tid >> 5;
    const int wm = wid & 3, wn = wid >> 2;
    const int r = lane >> 2, cq = lane & 3;
    const int row0 = blockIdx.y * BM;
    const int col0 = blockIdx.x * BN;

    const int aRow = lane & 15, aK = (lane >> 4) << 3;
    const int bK16 = lane & 15;
    const int bN8 = (lane >> 4) << 3;
    const unsigned aBase = (unsigned)__cvta_generic_to_shared(As);
    const unsigned bBase = (unsigned)__cvta_generic_to_shared(Bs);

    const __half* Ah = (const __half*)Av;
    const float*  Af = (const float*)Av;

    float acc[2][NTI][4];
#pragma unroll
    for (int mt = 0; mt < 2; mt++)
#pragma unroll
        for (int nt = 0; nt < NTI; nt++)
#pragma unroll
            for (int i = 0; i < 4; i++) acc[mt][nt][i] = 0.f;

#pragma unroll 1
    for (int ch = 0; ch < NCH; ch++) {
        const int kc0 = ch * KC;
        constexpr int AOPS = BM * KC / 8;        // 8-half segments

        if (AHALF) {
            // ---- stage A chunk via cp.async ----
#pragma unroll 4
            for (int i = tid; i < AOPS; i += 256) {
                const int row = i / (KC / 8);
                const int kh = (i % (KC / 8)) * 8;
                int srow = row0 + row;
                if (srow > M - 1) srow = M - 1;  // clamp: safe, discarded
                cp_async16(aBase + (unsigned)(row * KPA + kh) * 2,
                           Ah + (size_t)srow * K + kc0 + kh);
            }
            asm volatile("cp.async.commit_group;" ::: "memory");
        } else {
            // ---- stage A chunk: fp32 LDG + convert (deep MLP in prologue) ----
#pragma unroll 4
            for (int i = tid; i < AOPS; i += 256) {
                const int row = i / (KC / 8);
                const int kh = (i % (KC / 8)) * 8;
                int srow = row0 + row;
                if (srow > M - 1) srow = M - 1;
                const float* ap = Af + (size_t)srow * K + kc0 + kh;
                float4 f0 = *(const float4*)ap;
                float4 f1 = *(const float4*)(ap + 4);
                __half2 hv[4];
                hv[0] = __floats2half2_rn(f0.x, f0.y);
                hv[1] = __floats2half2_rn(f0.z, f0.w);
                hv[2] = __floats2half2_rn(f1.x, f1.y);
                hv[3] = __floats2half2_rn(f1.z, f1.w);
                *(uint4*)&As[row * KPA + kh] = *(uint4*)hv;
            }
        }

        // ---- stage B chunk ([k][n], vectorized, conflict-free) ----
#pragma unroll 4
        for (int idx = tid; idx < KC * (BN / 4); idx += 256) {
            const int k = idx / (BN / 4);
            const int n4 = (idx % (BN / 4)) * 4;
            float4 bv = *(const float4*)(Bg + (size_t)(kc0 + k) * N + col0 + n4);
            __half2* p = (__half2*)&Bs[k * NPAD + n4];
            p[0] = __floats2half2_rn(bv.x, bv.y);
            p[1] = __floats2half2_rn(bv.z, bv.w);
        }
        if (AHALF)
            asm volatile("cp.async.wait_group 0;" ::: "memory");
        __syncthreads();

        // ---- chunk mainloop: straight-line, zero barriers ----
#pragma unroll
        for (int it = 0; it < NTC; it++) {
            unsigned a[2][4], b[NTI][2];
#pragma unroll
            for (int mt = 0; mt < 2; mt++) {
                const int mb = wm * 32 + mt * 16;
                ldsm_x4(a[mt], aBase + (unsigned)((mb + aRow) * KPA + it * BK + aK) * 2);
            }
#pragma unroll
            for (int p = 0; p < NTI / 2; p++) {
                unsigned t[4];
                ldsm_x4_t(t, bBase + (unsigned)((it * BK + bK16) * NPAD + wn * WN + p * 16 + bN8) * 2);
                b[2 * p][0] = t[0]; b[2 * p][1] = t[1];
                b[2 * p + 1][0] = t[2]; b[2 * p + 1][1] = t[3];
            }
#pragma unroll
            for (int mt = 0; mt < 2; mt++)
#pragma unroll
                for (int nt = 0; nt < NTI; nt++)
                    mma_f16(acc[mt][nt], a[mt], b[nt]);
        }

        if (ch + 1 < NCH) __syncthreads();       // all reads done before restage
    }

    // ---- epilogue: store fp16 C ----
#pragma unroll
    for (int mt = 0; mt < 2; mt++) {
        const int m_lo = row0 + wm * 32 + mt * 16 + r;
        const int m_hi = m_lo + 8;
#pragma unroll
        for (int nt = 0; nt < NTI; nt++) {
            const int n = col0 + wn * WN + nt * 8 + cq * 2;
            if (m_lo < M)
                *(__half2*)(C + (size_t)m_lo * N + n) =
                    __floats2half2_rn(acc[mt][nt][0], acc[mt][nt][1]);
            if (m_hi < M)
                *(__half2*)(C + (size_t)m_hi * N + n) =
                    __floats2half2_rn(acc[mt][nt][2], acc[mt][nt][3]);
        }
    }

    // ---- fused alpha epilogue (atomic-free; red aliases As) ----
    float ps0[2] = {0.f, 0.f}, ps1[2] = {0.f, 0.f};
    float pd0[2] = {0.f, 0.f}, pd1[2] = {0.f, 0.f};
#pragma unroll
    for (int nt = 0; nt < NTI; nt++) {
#pragma unroll
        for (int j = 0; j < 2; j++) {
            const int c = wn * WN + nt * 8 + cq * 2 + j;
            const float a_ = av[c], d_ = dv[c];
#pragma unroll
            for (int mt = 0; mt < 2; mt++) {
                ps0[mt] = fmaf(acc[mt][nt][j],     a_, ps0[mt]);
                pd0[mt] = fmaf(acc[mt][nt][j],     d_, pd0[mt]);
                ps1[mt] = fmaf(acc[mt][nt][2 + j], a_, ps1[mt]);
                pd1[mt] = fmaf(acc[mt][nt][2 + j], d_, pd1[mt]);
            }
        }
    }
#pragma unroll
    for (int o = 1; o <= 2; o <<= 1) {
#pragma unroll
        for (int mt = 0; mt < 2; mt++) {
            ps0[mt] += __shfl_xor_sync(0xffffffffu, ps0[mt], o);
            ps1[mt] += __shfl_xor_sync(0xffffffffu, ps1[mt], o);
            pd0[mt] += __shfl_xor_sync(0xffffffffu, pd0[mt], o);
            pd1[mt] += __shfl_xor_sync(0xffffffffu, pd1[mt], o);
        }
    }
    __syncthreads();
    if (cq == 0) {
#pragma unroll
        for (int mt = 0; mt < 2; mt++) {
            const int lr = wm * 32 + mt * 16 + r;
            red_s[lr * 2 + wn] = ps0[mt];
            red_s[(lr + 8) * 2 + wn] = ps1[mt];
            red_d[lr * 2 + wn] = pd0[mt];
            red_d[(lr + 8) * 2 + wn] = pd1[mt];
        }
    }
    __syncthreads();
    if (tid < BM) {
        const int row = row0 + tid;
        if (row < M) {
            if (NH == 2) {
                sOut[(size_t)row * SSTR]     = red_s[tid * 2];
                sOut[(size_t)row * SSTR + 1] = red_s[tid * 2 + 1];
                dOut[(size_t)row * SSTR]     = red_d[tid * 2];
                dOut[(size_t)row * SSTR + 1] = red_d[tid * 2 + 1];
            } else {
                sOut[row] = red_s[tid * 2] + red_s[tid * 2 + 1];
                dOut[row] = red_d[tid * 2] + red_d[tid * 2 + 1];
            }
        }
    }
}

#define SMEM_G1 ((128 * (INDIM + 8) + INDIM * (128 + 8)) * 2)   // 69632 B
#define SMEM_G2 ((128 * (128 + 8) + 128 * (HD + 8)) * 2)        // 53248 B -> 2 CTA/SM

__global__ void __launch_bounds__(256) k_gemm1(const float* __restrict__ A,
                                               const float* __restrict__ B,
                                               const float* __restrict__ asrc,
                                               const float* __restrict__ adst) {
    mma_gemm<D1, INDIM, false, 128, 2, HEADS, INDIM>(
        A, B, g_h1h, NN,
        asrc + blockIdx.x * 128, adst + blockIdx.x * 128,
        g_as1 + blockIdx.x * 2, g_ad1 + blockIdx.x * 2);
}
__global__ void __launch_bounds__(256) k_gemm2(const float* __restrict__ B,
                                               const float* __restrict__ asrc,
                                               const float* __restrict__ adst) {
    mma_gemm<HD, D1, true, 64, 1, 1, 128>(g_g1h, B, g_h2h, NN, asrc, adst, g_as2, g_ad2);
}

// ---------------- CSR build (counting sort by dst) ----------------
__global__ void k_hist(const int* __restrict__ dst) {
    int i = blockIdx.x * blockDim.x + threadIdx.x;
    if (i < EE) atomicAdd(&g_deg[dst[i]], 1);
}

#define SCAN_B 512
#define SCAN_NB ((NN + SCAN_B - 1) / SCAN_B)   // 196

__global__ void k_scan1() {
    __shared__ int sm[SCAN_B];
    int i = blockIdx.x * SCAN_B + threadIdx.x;
    int v = (i < NN) ? g_deg[i] + 1 : 0;       // +1 = self-loop
    sm[threadIdx.x] = v;
    __syncthreads();
    for (int off = 1; off < SCAN_B; off <<= 1) {
        int t = (threadIdx.x >= off) ? sm[threadIdx.x - off] : 0;
        __syncthreads();
        sm[threadIdx.x] += t;
        __syncthreads();
    }
    if (i < NN) g_rowptr[i] = sm[threadIdx.x] - v;
    if (threadIdx.x == SCAN_B - 1) g_blksums[blockIdx.x] = sm[threadIdx.x];
}
__global__ void k_scan3() {
    __shared__ int sm[256], sme[256];
    const int t = threadIdx.x;
    int v = (t < SCAN_NB) ? g_blksums[t] : 0;
    sm[t] = v;
    __syncthreads();
    for (int off = 1; off < 256; off <<= 1) {
        int x = (t >= off) ? sm[t - off] : 0;
        __syncthreads();
        sm[t] += x;
        __syncthreads();
    }
    sme[t] = sm[t] - v;                         // exclusive
    __syncthreads();
    int i = blockIdx.x * blockDim.x + t;
    if (i < NN) {
        int r = g_rowptr[i] + sme[i / SCAN_B];
        g_rowptr[i] = r;
        g_cursor[i] = r;
        g_deg[i] = 0;                           // re-zero for next launch's hist
    } else if (i == NN) {
        g_rowptr[NN] = ET;
    }
}
__global__ void k_scatter(const int* __restrict__ ei) {
    int i = blockIdx.x * blockDim.x + threadIdx.x;
    if (i >= ET) return;
    int s, d;
    if (i < EE) { s = ei[i]; d = ei[EE + i]; }
    else        { s = d = i - EE; }
    int pos = atomicAdd(&g_cursor[d], 1);
    g_srcs[pos] = s;
}

// ------- layer-1 aggregation: one warp per dst node, single pass -------
__global__ void __launch_bounds__(1024) k_agg1(const float* __restrict__ b1) {
    int gw = blockIdx.x * 32 + (threadIdx.x >> 5);
    if (gw >= NN) return;
    const int lane = threadIdx.x & 31;
    const int v = gw;
    const int r0 = g_rowptr[v], r1 = g_rowptr[v + 1];
    const float4 adv = ((const float4*)g_ad1)[v];

    const int head = lane >> 3;                // 8 lanes per head
    const float adh = head == 0 ? adv.x : head == 1 ? adv.y : head == 2 ? adv.z : adv.w;
    const float* asb = g_as1 + head;

    float S = 0.f;
    float acc[8];
#pragma unroll
    for (int i = 0; i < 8; i++) acc[i] = 0.f;

    const __half* h1b = g_h1h + lane * 8;
    int e = r0;
    for (; e + 4 <= r1; e += 4) {
        int sa = g_srcs[e], sb = g_srcs[e + 1], sc = g_srcs[e + 2], sd = g_srcs[e + 3];
        float wa = asb[sa * 4], wb = asb[sb * 4], wc = asb[sc * 4], wd = asb[sd * 4];
        uint4 ha = *(const uint4*)(h1b + (size_t)sa * D1);
        uint4 hb = *(const uint4*)(h1b + (size_t)sb * D1);
        uint4 hc = *(const uint4*)(h1b + (size_t)sc * D1);
        uint4 hd = *(const uint4*)(h1b + (size_t)sd * D1);
        float aa = __expf(lrelu(wa + adh) - SM_OFF);
        float ab = __expf(lrelu(wb + adh) - SM_OFF);
        float ac = __expf(lrelu(wc + adh) - SM_OFF);
        float ad = __expf(lrelu(wd + adh) - SM_OFF);
        S += (aa + ab) + (ac + ad);
        const __half2* pa = (const __half2*)&ha;
        const __half2* pb = (const __half2*)&hb;
        const __half2* pc = (const __half2*)&hc;
        const __half2* pd = (const __half2*)&hd;
#pragma unroll
        for (int j = 0; j < 4; j++) {
            float2 fa = __half22float2(pa[j]);
            float2 fb = __half22float2(pb[j]);
            float2 fc = __half22float2(pc[j]);
            float2 fd = __half22float2(pd[j]);
            acc[2 * j]     = fmaf(fa.x, aa, fmaf(fb.x, ab, fmaf(fc.x, ac, fmaf(fd.x, ad, acc[2 * j]))));
            acc[2 * j + 1] = fmaf(fa.y, aa, fmaf(fb.y, ab, fmaf(fc.y, ac, fmaf(fd.y, ad, acc[2 * j + 1]))));
        }
    }
    for (; e < r1; e++) {
        int s = g_srcs[e];
        float a = __expf(lrelu(asb[s * 4] + adh) - SM_OFF);
        S += a;
        uint4 hv = *(const uint4*)(h1b + (size_t)s * D1);
        const __half2* h2 = (const __half2*)&hv;
#pragma unroll
        for (int j = 0; j < 4; j++) {
            float2 f = __half22float2(h2[j]);
            acc[2 * j]     = fmaf(f.x, a, acc[2 * j]);
            acc[2 * j + 1] = fmaf(f.y, a, acc[2 * j + 1]);
        }
    }

    const float inv = 1.f / S;
    const float* bb = b1 + lane * 8;
    __half2 oh[4];
#pragma unroll
    for (int j = 0; j < 4; j++)
        oh[j] = __floats2half2_rn(eluf(fmaf(acc[2 * j], inv, bb[2 * j])),
                                  eluf(fmaf(acc[2 * j + 1], inv, bb[2 * j + 1])));
    *(uint4*)(g_g1h + (size_t)v * D1 + lane * 8) = *(uint4*)oh;
}

// ------- layer-2 aggregation + ELU + final linear, single pass -------
__global__ void __launch_bounds__(1024) k_agg2(const float* __restrict__ b2,
                                               const float* __restrict__ lw,
                                               const float* __restrict__ lb,
                                               float* __restrict__ out) {
    int gw = blockIdx.x * 32 + (threadIdx.x >> 5);
    if (gw >= NN) return;
    const int lane = threadIdx.x & 31;
    const int v = gw;
    const int r0 = g_rowptr[v], r1 = g_rowptr[v + 1];
    const float adv = g_ad2[v];

    float S = 0.f;
    float2 acc = make_float2(0.f, 0.f);
    const __half* h2b = g_h2h + lane * 2;
    int e = r0;
    for (; e + 4 <= r1; e += 4) {
        int sa = g_srcs[e], sb = g_srcs[e + 1], sc = g_srcs[e + 2], sd = g_srcs[e + 3];
        float wa = g_as2[sa], wb = g_as2[sb], wc = g_as2[sc], wd = g_as2[sd];
        __half2 xa = *(const __half2*)(h2b + (size_t)sa * HD);
        __half2 xb = *(const __half2*)(h2b + (size_t)sb * HD);
        __half2 xc = *(const __half2*)(h2b + (size_t)sc * HD);
        __half2 xd = *(const __half2*)(h2b + (size_t)sd * HD);
        float aa = __expf(lrelu(wa + adv) - SM_OFF);
        float ab = __expf(lrelu(wb + adv) - SM_OFF);
        float ac = __expf(lrelu(wc + adv) - SM_OFF);
        float ad = __expf(lrelu(wd + adv) - SM_OFF);
        S += (aa + ab) + (ac + ad);
        float2 fa = __half22float2(xa), fb = __half22float2(xb);
        float2 fc = __half22float2(xc), fd = __half22float2(xd);
        acc.x = fmaf(fa.x, aa, fmaf(fb.x, ab, fmaf(fc.x, ac, fmaf(fd.x, ad, acc.x))));
        acc.y = fmaf(fa.y, aa, fmaf(fb.y, ab, fmaf(fc.y, ac, fmaf(fd.y, ad, acc.y))));
    }
    for (; e < r1; e++) {
        int s = g_srcs[e];
        float a = __expf(lrelu(g_as2[s] + adv) - SM_OFF);
        S += a;
        float2 x = __half22float2(*(const __half2*)(h2b + (size_t)s * HD));
        acc.x = fmaf(x.x, a, acc.x);
        acc.y = fmaf(x.y, a, acc.y);
    }

    const float inv = 1.f / S;
    const int d = 2 * lane;
    float t0 = eluf(fmaf(acc.x, inv, b2[d]));
    float t1 = eluf(fmaf(acc.y, inv, b2[d + 1]));
    float y0 = t0 * lw[d * 2]     + t1 * lw[d * 2 + 2];
    float y1 = t0 * lw[d * 2 + 1] + t1 * lw[d * 2 + 3];
#pragma unroll
    for (int o = 16; o; o >>= 1) {
        y0 += __shfl_xor_sync(0xffffffffu, y0, o);
        y1 += __shfl_xor_sync(0xffffffffu, y1, o);
    }
    if (lane == 0) {
        out[2 * v]     = y0 + lb[0];
        out[2 * v + 1] = y1 + lb[1];
    }
}

// ---------------- launch ----------------
extern "C" void kernel_launch(void* const* d_in, const int* in_sizes, int n_in,
                              void* d_out, int out_size) {
    const float* x      = (const float*)d_in[0];
    const int*   ei     = (const int*)d_in[1];     // int32: jax default x64 disabled
    const float* W1     = (const float*)d_in[2];
    const float* a_src1 = (const float*)d_in[3];
    const float* a_dst1 = (const float*)d_in[4];
    const float* b1     = (const float*)d_in[5];
    const float* W2     = (const float*)d_in[6];
    const float* a_src2 = (const float*)d_in[7];
    const float* a_dst2 = (const float*)d_in[8];
    const float* b2     = (const float*)d_in[9];
    const float* lw     = (const float*)d_in[10];
    const float* lb     = (const float*)d_in[11];
    float*       out    = (float*)d_out;

    static cudaStream_t s1 = nullptr;
    static cudaEvent_t evRoot = nullptr, evCsr = nullptr;
    if (s1 == nullptr) {
        cudaStreamCreateWithFlags(&s1, cudaStreamNonBlocking);
        cudaEventCreateWithFlags(&evRoot, cudaEventDisableTiming);
        cudaEventCreateWithFlags(&evCsr, cudaEventDisableTiming);
        cudaFuncSetAttribute(k_gemm1, cudaFuncAttributeMaxDynamicSharedMemorySize, SMEM_G1);
        cudaFuncSetAttribute(k_gemm2, cudaFuncAttributeMaxDynamicSharedMemorySize, SMEM_G2);
    }

    // fork: CSR chain on s1, GEMM1 (direct fp32 A) on main stream
    cudaEventRecord(evRoot, 0);
    cudaStreamWaitEvent(s1, evRoot, 0);

    k_hist<<<(EE + 255) / 256, 256, 0, s1>>>(ei + EE);          // #1
    k_scan1<<<SCAN_NB, SCAN_B, 0, s1>>>();                      // #2
    k_scan3<<<(NN + 1 + 255) / 256, 256, 0, s1>>>();            // #3

    k_gemm1<<<dim3(2, (NN + 127) / 128), 256, SMEM_G1>>>(x, W1, a_src1, a_dst1);  // #4 (profiled)

    k_scatter<<<(ET + 255) / 256, 256, 0, s1>>>(ei);            // #5
    cudaEventRecord(evCsr, s1);

    // join: agg1 needs CSR + gemm1(+fused alphas)
    cudaStreamWaitEvent(0, evCsr, 0);
    k_agg1<<<(NN + 31) / 32, 1024>>>(b1);                       // #6

    // layer 2
    k_gemm2<<<dim3(1, (NN + 127) / 128), 256, SMEM_G2>>>(W2, a_src2, a_dst2);  // #7
    k_agg2<<<(NN + 31) / 32, 1024>>>(b2, lw, lb, out);          // #8
}